// round 1
// baseline (speedup 1.0000x reference)
#include <cuda_runtime.h>
#include <cstdint>
#include <cstddef>

// ---------------------------------------------------------------------------
// Problem constants: B=2, D=H=W=T=16, C=96, NH=4 (hd=24), window 4^4=256,
// shift 2. Windows: 512 total (256/batch), 256 tokens each. Tokens = 131072.
// ---------------------------------------------------------------------------
#define TOKENS   131072
#define CDIM     96
#define NWIN     512
#define NTOK     256
#define HD       24
#define NHEADS   4
#define HIDDEN_DIM 384

// Scratch (device globals: allocation-free per harness rules)
__device__ float g_xw  [(size_t)TOKENS * CDIM];        // LN1 + shift + partition
__device__ float g_qkv [(size_t)3 * TOKENS * CDIM];    // [s][w][h][n][d]
__device__ float g_attn[(size_t)TOKENS * CDIM];        // attention out, window order
__device__ float g_x2  [(size_t)TOKENS * CDIM];        // after first residual (natural)
__device__ float g_xn2 [(size_t)TOKENS * CDIM];        // LN2
__device__ float g_h   [(size_t)TOKENS * HIDDEN_DIM];  // fc1+gelu

// window-token index t -> natural flat token index (applies +2 roll per dim,
// which is simultaneously the gather source for the forward shift and the
// scatter destination for the reverse shift).
__device__ __forceinline__ int nat_index(int t) {
    int r = t & 255, w = t >> 8;
    int b = w >> 8, wi = w & 255;
    int d  = ((((wi >> 6) & 3) << 2) | ((r >> 6) & 3));
    int hh = ((((wi >> 4) & 3) << 2) | ((r >> 4) & 3));
    int ww = ((((wi >> 2) & 3) << 2) | ((r >> 2) & 3));
    int tt = (((wi & 3) << 2) | (r & 3));
    d = (d + 2) & 15; hh = (hh + 2) & 15; ww = (ww + 2) & 15; tt = (tt + 2) & 15;
    return (((b * 16 + d) * 16 + hh) * 16 + ww) * 16 + tt;
}

// Swin shifted-window mask group id: per dim, coord in [0,12)/[12,14)/[14,16).
// mask[i][j] = -100 iff group(i) != group(j). Exactly reproduces _compute_mask().
__device__ __forceinline__ int group_of(int wi, int r) {
    int g = 0;
#pragma unroll
    for (int a = 3; a >= 0; --a) {
        int c = ((((wi >> (2 * a)) & 3) << 2) | ((r >> (2 * a)) & 3));
        int s = (c < 12) ? 0 : ((c < 14) ? 1 : 2);
        g = g * 3 + s;
    }
    return g;
}

// ---------------------------------------------------------------------------
// LayerNorm (warp per token). gather=1: read via nat_index (LN1+shift+partition)
// ---------------------------------------------------------------------------
__global__ void ln_kernel(const float* __restrict__ x,
                          const float* __restrict__ gamma,
                          const float* __restrict__ beta,
                          float* __restrict__ out, int gather) {
    int t = blockIdx.x * 8 + (threadIdx.x >> 5);
    int lane = threadIdx.x & 31;
    int src = gather ? nat_index(t) : t;
    const float* row = x + (size_t)src * CDIM;
    float v0 = row[lane], v1 = row[lane + 32], v2 = row[lane + 64];
    float s = v0 + v1 + v2;
    float sq = v0 * v0 + v1 * v1 + v2 * v2;
#pragma unroll
    for (int o = 16; o; o >>= 1) {
        s  += __shfl_xor_sync(0xffffffffu, s, o);
        sq += __shfl_xor_sync(0xffffffffu, sq, o);
    }
    float mean = s * (1.f / 96.f);
    float var = sq * (1.f / 96.f) - mean * mean;
    float rstd = rsqrtf(var + 1e-5f);
    float* op = out + (size_t)t * CDIM;
    op[lane]      = (v0 - mean) * rstd * gamma[lane]      + beta[lane];
    op[lane + 32] = (v1 - mean) * rstd * gamma[lane + 32] + beta[lane + 32];
    op[lane + 64] = (v2 - mean) * rstd * gamma[lane + 64] + beta[lane + 64];
}

// ---------------------------------------------------------------------------
// Tiled fp32 GEMM: C[M,N] = A[M,K] @ W[N,K]^T, BM=64, BN=96, BK=32,
// 256 threads, 4x6 microtile each. Epilogue variants fused.
// ---------------------------------------------------------------------------
#define BM 64
#define BN 96
#define BK 32

enum { EPI_QKV = 0, EPI_PROJ = 1, EPI_FC1 = 2, EPI_FC2 = 3 };

template <int E>
__global__ void gemm_kernel(const float* __restrict__ A, int lda, int K,
                            const float* __restrict__ W,
                            const float* __restrict__ bias,
                            const float* __restrict__ res,
                            float* __restrict__ out) {
    __shared__ float As[BK][BM + 4];   // k-major
    __shared__ float Ws[BK][BN + 4];   // k-major

    const int tid = threadIdx.x;
    const int m0 = blockIdx.x * BM;
    const int nblk = blockIdx.y;
    const int n0 = nblk * BN;
    const int tm = tid >> 4;           // 0..15 -> 4 rows each
    const int tn = tid & 15;           // 0..15 -> 6 cols each

    float acc[4][6];
#pragma unroll
    for (int i = 0; i < 4; ++i)
#pragma unroll
        for (int j = 0; j < 6; ++j) acc[i][j] = 0.f;

    for (int kc = 0; kc < K; kc += BK) {
        // A tile: 64 rows x 32 k -> 512 float4
#pragma unroll
        for (int it = 0; it < 2; ++it) {
            int idx = tid + it * 256;
            int row = idx >> 3, c4 = (idx & 7) << 2;
            float4 v = *(const float4*)(A + (size_t)(m0 + row) * lda + kc + c4);
            As[c4 + 0][row] = v.x; As[c4 + 1][row] = v.y;
            As[c4 + 2][row] = v.z; As[c4 + 3][row] = v.w;
        }
        // W tile: 96 rows x 32 k -> 768 float4
#pragma unroll
        for (int it = 0; it < 3; ++it) {
            int idx = tid + it * 256;
            int row = idx >> 3, c4 = (idx & 7) << 2;
            float4 v = *(const float4*)(W + (size_t)(n0 + row) * K + kc + c4);
            Ws[c4 + 0][row] = v.x; Ws[c4 + 1][row] = v.y;
            Ws[c4 + 2][row] = v.z; Ws[c4 + 3][row] = v.w;
        }
        __syncthreads();
#pragma unroll
        for (int k = 0; k < BK; ++k) {
            float4 a = *(const float4*)&As[k][tm << 2];
            float2 b0 = *(const float2*)&Ws[k][tn * 6 + 0];
            float2 b1 = *(const float2*)&Ws[k][tn * 6 + 2];
            float2 b2 = *(const float2*)&Ws[k][tn * 6 + 4];
            float av[4] = {a.x, a.y, a.z, a.w};
            float bv[6] = {b0.x, b0.y, b1.x, b1.y, b2.x, b2.y};
#pragma unroll
            for (int i = 0; i < 4; ++i)
#pragma unroll
                for (int j = 0; j < 6; ++j) acc[i][j] += av[i] * bv[j];
        }
        __syncthreads();
    }

    // ---- epilogues ----
    if (E == EPI_QKV) {
        const float scale = (nblk == 0) ? 0.20412414523193154f : 1.0f;  // hd^-0.5
#pragma unroll
        for (int i = 0; i < 4; ++i) {
            int m = m0 + (tm << 2) + i;
            int w = m >> 8, r = m & 255;
#pragma unroll
            for (int j = 0; j < 6; ++j) {
                int nl = tn * 6 + j;
                int h = nl / 24, dd = nl % 24;
                float v = (acc[i][j] + bias[n0 + nl]) * scale;
                out[(((size_t)nblk * NWIN + w) * NHEADS + h) * (NTOK * HD) + r * HD + dd] = v;
            }
        }
    } else if (E == EPI_PROJ) {
#pragma unroll
        for (int i = 0; i < 4; ++i) {
            int m = m0 + (tm << 2) + i;
            size_t dst = (size_t)nat_index(m) * CDIM;
#pragma unroll
            for (int j = 0; j < 6; ++j) {
                int nl = tn * 6 + j;
                out[dst + nl] = res[dst + nl] + acc[i][j] + bias[nl];
            }
        }
    } else if (E == EPI_FC1) {
#pragma unroll
        for (int i = 0; i < 4; ++i) {
            int m = m0 + (tm << 2) + i;
#pragma unroll
            for (int j = 0; j < 6; ++j) {
                int n = n0 + tn * 6 + j;
                float v = acc[i][j] + bias[n];
                float gel = 0.5f * v * (1.f + erff(v * 0.70710678118654752f));
                out[(size_t)m * HIDDEN_DIM + n] = gel;
            }
        }
    } else {  // EPI_FC2
#pragma unroll
        for (int i = 0; i < 4; ++i) {
            int m = m0 + (tm << 2) + i;
#pragma unroll
            for (int j = 0; j < 6; ++j) {
                int nl = tn * 6 + j;
                out[(size_t)m * CDIM + nl] = res[(size_t)m * CDIM + nl] + acc[i][j] + bias[nl];
            }
        }
    }
}

// ---------------------------------------------------------------------------
// Attention: one block per (window, head). K,V in smem; thread = query row;
// single pass online softmax; mask derived analytically from group ids.
// ---------------------------------------------------------------------------
__global__ void attn_kernel(const float* __restrict__ qkv,
                            float* __restrict__ attnout) {
    extern __shared__ float sm[];
    float* ks = sm;                                   // 256*24
    float* vs = sm + NTOK * HD;                       // 256*24
    unsigned char* grp = (unsigned char*)(sm + 2 * NTOK * HD);  // 256

    const int w = blockIdx.x, h = blockIdx.y;
    const int tid = threadIdx.x;
    const size_t head_stride = (size_t)NTOK * HD;
    const float* kbase = qkv + (((size_t)1 * NWIN + w) * NHEADS + h) * head_stride;
    const float* vbase = qkv + (((size_t)2 * NWIN + w) * NHEADS + h) * head_stride;

#pragma unroll
    for (int it = 0; it < 6; ++it) {   // 6144 floats = 1536 float4 / 256 thr
        int idx = (tid + it * 256) * 4;
        *(float4*)(ks + idx) = *(const float4*)(kbase + idx);
        *(float4*)(vs + idx) = *(const float4*)(vbase + idx);
    }
    grp[tid] = (unsigned char)group_of(w & 255, tid);
    __syncthreads();

    const float* qrow = qkv + (((size_t)0 * NWIN + w) * NHEADS + h) * head_stride + tid * HD;
    float q[HD];
#pragma unroll
    for (int d = 0; d < HD; d += 4) {
        float4 v = *(const float4*)(qrow + d);
        q[d] = v.x; q[d + 1] = v.y; q[d + 2] = v.z; q[d + 3] = v.w;
    }
    const int gi = grp[tid];

    float mmax = -1e30f, l = 0.f;
    float o[HD];
#pragma unroll
    for (int d = 0; d < HD; ++d) o[d] = 0.f;

    for (int j = 0; j < NTOK; ++j) {
        const float* kj = ks + j * HD;
        float s = 0.f;
#pragma unroll
        for (int d = 0; d < HD; ++d) s += q[d] * kj[d];
        s += (grp[j] == gi) ? 0.f : -100.f;
        float mn = fmaxf(mmax, s);
        float alpha = __expf(mmax - mn);
        float p = __expf(s - mn);
        l = l * alpha + p;
        const float* vj = vs + j * HD;
#pragma unroll
        for (int d = 0; d < HD; ++d) o[d] = o[d] * alpha + p * vj[d];
        mmax = mn;
    }
    float inv = 1.f / l;
    float* op = attnout + ((size_t)w * NTOK + tid) * CDIM + h * HD;
#pragma unroll
    for (int d = 0; d < HD; ++d) op[d] = o[d] * inv;
}

// ---------------------------------------------------------------------------
extern "C" void kernel_launch(void* const* d_in, const int* in_sizes, int n_in,
                              void* d_out, int out_size) {
    (void)in_sizes; (void)n_in; (void)out_size;
    const float* x       = (const float*)d_in[0];
    // d_in[1] = mask_matrix (unused: mask derived analytically)
    const float* norm1_g = (const float*)d_in[2];
    const float* norm1_b = (const float*)d_in[3];
    const float* qkv_w   = (const float*)d_in[4];
    const float* qkv_b   = (const float*)d_in[5];
    const float* proj_w  = (const float*)d_in[6];
    const float* proj_b  = (const float*)d_in[7];
    const float* norm2_g = (const float*)d_in[8];
    const float* norm2_b = (const float*)d_in[9];
    const float* fc1_w   = (const float*)d_in[10];
    const float* fc1_b   = (const float*)d_in[11];
    const float* fc2_w   = (const float*)d_in[12];
    const float* fc2_b   = (const float*)d_in[13];
    float* out = (float*)d_out;

    float *xw, *qkv, *attn, *x2, *xn2, *hbuf;
    cudaGetSymbolAddress((void**)&xw,   g_xw);
    cudaGetSymbolAddress((void**)&qkv,  g_qkv);
    cudaGetSymbolAddress((void**)&attn, g_attn);
    cudaGetSymbolAddress((void**)&x2,   g_x2);
    cudaGetSymbolAddress((void**)&xn2,  g_xn2);
    cudaGetSymbolAddress((void**)&hbuf, g_h);

    const int attn_smem = (2 * NTOK * HD) * 4 + 256;  // 49408 B
    cudaFuncSetAttribute(attn_kernel, cudaFuncAttributeMaxDynamicSharedMemorySize, attn_smem);

    // 1) LN1 + shift + window partition
    ln_kernel<<<TOKENS / 8, 256>>>(x, norm1_g, norm1_b, xw, 1);
    // 2) QKV projection (sections q/k/v via blockIdx.y), scaled q
    gemm_kernel<EPI_QKV><<<dim3(TOKENS / BM, 3), 256>>>(xw, CDIM, CDIM, qkv_w, qkv_b, nullptr, qkv);
    // 3) windowed attention with analytic shift mask
    attn_kernel<<<dim3(NWIN, NHEADS), 256, attn_smem>>>(qkv, attn);
    // 4) proj + reverse partition + reverse shift + residual
    gemm_kernel<EPI_PROJ><<<dim3(TOKENS / BM, 1), 256>>>(attn, CDIM, CDIM, proj_w, proj_b, x, x2);
    // 5) LN2
    ln_kernel<<<TOKENS / 8, 256>>>(x2, norm2_g, norm2_b, xn2, 0);
    // 6) fc1 + exact GELU
    gemm_kernel<EPI_FC1><<<dim3(TOKENS / BM, HIDDEN_DIM / BN), 256>>>(xn2, CDIM, CDIM, fc1_w, fc1_b, nullptr, hbuf);
    // 7) fc2 + residual -> output
    gemm_kernel<EPI_FC2><<<dim3(TOKENS / BM, 1), 256>>>(hbuf, HIDDEN_DIM, HIDDEN_DIM, fc2_w, fc2_b, x2, out);
}

// round 2
// speedup vs baseline: 1.6315x; 1.6315x over previous
#include <cuda_runtime.h>
#include <cstdint>
#include <cstddef>

#define TOKENS   131072
#define CDIM     96
#define NWIN     512
#define NTOK     256
#define HD       24
#define NHEADS   4
#define HIDDEN_DIM 384

typedef unsigned long long ull;

// Scratch
__device__ float g_xw  [(size_t)TOKENS * CDIM];
__device__ float g_qkv [(size_t)3 * TOKENS * CDIM];
__device__ float g_attn[(size_t)TOKENS * CDIM];
__device__ float g_x2  [(size_t)TOKENS * CDIM];
__device__ float g_xn2 [(size_t)TOKENS * CDIM];
__device__ float g_h   [(size_t)TOKENS * HIDDEN_DIM];

__device__ __forceinline__ int nat_index(int t) {
    int r = t & 255, w = t >> 8;
    int b = w >> 8, wi = w & 255;
    int d  = ((((wi >> 6) & 3) << 2) | ((r >> 6) & 3));
    int hh = ((((wi >> 4) & 3) << 2) | ((r >> 4) & 3));
    int ww = ((((wi >> 2) & 3) << 2) | ((r >> 2) & 3));
    int tt = (((wi & 3) << 2) | (r & 3));
    d = (d + 2) & 15; hh = (hh + 2) & 15; ww = (ww + 2) & 15; tt = (tt + 2) & 15;
    return (((b * 16 + d) * 16 + hh) * 16 + ww) * 16 + tt;
}

__device__ __forceinline__ int group_of(int wi, int r) {
    int g = 0;
#pragma unroll
    for (int a = 3; a >= 0; --a) {
        int c = ((((wi >> (2 * a)) & 3) << 2) | ((r >> (2 * a)) & 3));
        int s = (c < 12) ? 0 : ((c < 14) ? 1 : 2);
        g = g * 3 + s;
    }
    return g;
}

// packed fp32x2 helpers (sm_103a)
__device__ __forceinline__ ull pk2(float a, float b) {
    ull r; asm("mov.b64 %0,{%1,%2};" : "=l"(r) : "f"(a), "f"(b)); return r;
}
__device__ __forceinline__ void fma2(ull& d, ull a, ull b) {
    asm("fma.rn.f32x2 %0,%1,%2,%0;" : "+l"(d) : "l"(a), "l"(b));
}
__device__ __forceinline__ void unpk2(float& a, float& b, ull v) {
    asm("mov.b64 {%0,%1},%2;" : "=f"(a), "=f"(b) : "l"(v));
}
__device__ __forceinline__ uint32_t to_tf32(float v) {
    uint32_t r; asm("cvt.rna.tf32.f32 %0,%1;" : "=r"(r) : "f"(v)); return r;
}

// ---------------------------------------------------------------------------
// LayerNorm (warp per token)
// ---------------------------------------------------------------------------
__global__ void ln_kernel(const float* __restrict__ x,
                          const float* __restrict__ gamma,
                          const float* __restrict__ beta,
                          float* __restrict__ out, int gather) {
    int t = blockIdx.x * 8 + (threadIdx.x >> 5);
    int lane = threadIdx.x & 31;
    int src = gather ? nat_index(t) : t;
    const float* row = x + (size_t)src * CDIM;
    float v0 = row[lane], v1 = row[lane + 32], v2 = row[lane + 64];
    float s = v0 + v1 + v2;
    float sq = v0 * v0 + v1 * v1 + v2 * v2;
#pragma unroll
    for (int o = 16; o; o >>= 1) {
        s  += __shfl_xor_sync(0xffffffffu, s, o);
        sq += __shfl_xor_sync(0xffffffffu, sq, o);
    }
    float mean = s * (1.f / 96.f);
    float var = sq * (1.f / 96.f) - mean * mean;
    float rstd = rsqrtf(var + 1e-5f);
    float* op = out + (size_t)t * CDIM;
    op[lane]      = (v0 - mean) * rstd * gamma[lane]      + beta[lane];
    op[lane + 32] = (v1 - mean) * rstd * gamma[lane + 32] + beta[lane + 32];
    op[lane + 64] = (v2 - mean) * rstd * gamma[lane + 64] + beta[lane + 64];
}

// ---------------------------------------------------------------------------
// tf32 tensor-core GEMM: C[M,N] = A[M,K] @ W[N,K]^T
// block 256 thr (8 warps), BM=128, BN=96, BK=32; warp tile 32x48,
// mma.sync m16n8k8 tf32, fp32 accumulate. Fused epilogues.
// ---------------------------------------------------------------------------
#define BMX 128
#define BNX 96
#define BKX 32
#define SSTR 36   // row stride: bank = (4*row + col) % 32 -> frag loads conflict-free

enum { EPI_QKV = 0, EPI_PROJ = 1, EPI_FC1 = 2, EPI_FC2 = 3 };

__device__ __forceinline__ void mma_tf32(float4& d, const uint32_t a[4], const uint32_t b[2]) {
    asm("mma.sync.aligned.m16n8k8.row.col.f32.tf32.tf32.f32 "
        "{%0,%1,%2,%3},{%4,%5,%6,%7},{%8,%9},{%0,%1,%2,%3};"
        : "+f"(d.x), "+f"(d.y), "+f"(d.z), "+f"(d.w)
        : "r"(a[0]), "r"(a[1]), "r"(a[2]), "r"(a[3]), "r"(b[0]), "r"(b[1]));
}

template <int E>
__global__ void __launch_bounds__(256) gemm_tc(const float* __restrict__ A, int lda, int K,
                                               const float* __restrict__ W,
                                               const float* __restrict__ bias,
                                               const float* __restrict__ res,
                                               float* __restrict__ out) {
    __shared__ uint32_t As[BMX][SSTR];
    __shared__ uint32_t Ws[BNX][SSTR];

    const int tid  = threadIdx.x;
    const int warp = tid >> 5, lane = tid & 31;
    const int gid  = lane >> 2, tig = lane & 3;
    const int wm   = (warp >> 1) * 32;
    const int wn   = (warp & 1) * 48;
    const int m0   = blockIdx.x * BMX;
    const int nblk = blockIdx.y;
    const int n0   = nblk * BNX;

    float4 acc[2][6];
#pragma unroll
    for (int i = 0; i < 2; ++i)
#pragma unroll
        for (int j = 0; j < 6; ++j) acc[i][j] = make_float4(0.f, 0.f, 0.f, 0.f);

    for (int kc = 0; kc < K; kc += BKX) {
        // A tile: 128x32 -> 1024 float4
#pragma unroll
        for (int it = 0; it < 4; ++it) {
            int idx = tid + it * 256;
            int row = idx >> 3, c4 = (idx & 7) << 2;
            float4 v = *(const float4*)(A + (size_t)(m0 + row) * lda + kc + c4);
            As[row][c4 + 0] = to_tf32(v.x); As[row][c4 + 1] = to_tf32(v.y);
            As[row][c4 + 2] = to_tf32(v.z); As[row][c4 + 3] = to_tf32(v.w);
        }
        // W tile: 96x32 -> 768 float4
#pragma unroll
        for (int it = 0; it < 3; ++it) {
            int idx = tid + it * 256;
            int row = idx >> 3, c4 = (idx & 7) << 2;
            float4 v = *(const float4*)(W + (size_t)(n0 + row) * K + kc + c4);
            Ws[row][c4 + 0] = to_tf32(v.x); Ws[row][c4 + 1] = to_tf32(v.y);
            Ws[row][c4 + 2] = to_tf32(v.z); Ws[row][c4 + 3] = to_tf32(v.w);
        }
        __syncthreads();
#pragma unroll
        for (int ks = 0; ks < 4; ++ks) {
            const int k = ks * 8;
            uint32_t a[2][4];
#pragma unroll
            for (int mi = 0; mi < 2; ++mi) {
                int r = wm + mi * 16 + gid;
                a[mi][0] = As[r][k + tig];
                a[mi][1] = As[r + 8][k + tig];
                a[mi][2] = As[r][k + tig + 4];
                a[mi][3] = As[r + 8][k + tig + 4];
            }
            uint32_t b[6][2];
#pragma unroll
            for (int ni = 0; ni < 6; ++ni) {
                int n = wn + ni * 8 + gid;
                b[ni][0] = Ws[n][k + tig];
                b[ni][1] = Ws[n][k + tig + 4];
            }
#pragma unroll
            for (int mi = 0; mi < 2; ++mi)
#pragma unroll
                for (int ni = 0; ni < 6; ++ni) mma_tf32(acc[mi][ni], a[mi], b[ni]);
        }
        __syncthreads();
    }

    // epilogue: element (row, col) pairs per fragment
#pragma unroll
    for (int mi = 0; mi < 2; ++mi) {
        int r0 = m0 + wm + mi * 16 + gid;   // rows r0, r0+8
#pragma unroll
        for (int half = 0; half < 2; ++half) {
            int m = r0 + half * 8;
            size_t proj_dst = 0;
            if (E == EPI_PROJ) proj_dst = (size_t)nat_index(m) * CDIM;
            int w = m >> 8, rr = m & 255;
#pragma unroll
            for (int ni = 0; ni < 6; ++ni) {
                float v0 = half ? acc[mi][ni].z : acc[mi][ni].x;
                float v1 = half ? acc[mi][ni].w : acc[mi][ni].y;
#pragma unroll
                for (int e = 0; e < 2; ++e) {
                    int nl = wn + ni * 8 + tig * 2 + e;
                    float v = (e ? v1 : v0) + bias[n0 + nl];
                    if (E == EPI_QKV) {
                        const float scale = (nblk == 0) ? 0.20412414523193154f : 1.0f;
                        int h = nl / 24, dd = nl % 24;
                        out[(((size_t)nblk * NWIN + w) * NHEADS + h) * (NTOK * HD) + rr * HD + dd] = v * scale;
                    } else if (E == EPI_PROJ) {
                        out[proj_dst + nl] = res[proj_dst + nl] + v;
                    } else if (E == EPI_FC1) {
                        float gel = 0.5f * v * (1.f + erff(v * 0.70710678118654752f));
                        out[(size_t)m * HIDDEN_DIM + n0 + nl] = gel;
                    } else {
                        out[(size_t)m * CDIM + nl] = res[(size_t)m * CDIM + nl] + v;
                    }
                }
            }
        }
    }
}

// ---------------------------------------------------------------------------
// Attention: block per (window, head); thread = query row. K,V in smem
// (warp-broadcast 64-bit reads). No online rescale (scores tiny, masked =
// s-100 -> exp ~ 1e-44). Packed fp32x2 FMAs.
// ---------------------------------------------------------------------------
__global__ void __launch_bounds__(256) attn_kernel(const float* __restrict__ qkv,
                                                   float* __restrict__ attnout) {
    extern __shared__ float sm[];
    float* ks = sm;
    float* vs = sm + NTOK * HD;
    unsigned char* grp = (unsigned char*)(sm + 2 * NTOK * HD);

    const int w = blockIdx.x, h = blockIdx.y;
    const int tid = threadIdx.x;
    const size_t head_stride = (size_t)NTOK * HD;
    const float* kbase = qkv + (((size_t)1 * NWIN + w) * NHEADS + h) * head_stride;
    const float* vbase = qkv + (((size_t)2 * NWIN + w) * NHEADS + h) * head_stride;

#pragma unroll
    for (int it = 0; it < 6; ++it) {
        int idx = (tid + it * 256) * 4;
        *(float4*)(ks + idx) = *(const float4*)(kbase + idx);
        *(float4*)(vs + idx) = *(const float4*)(vbase + idx);
    }
    grp[tid] = (unsigned char)group_of(w & 255, tid);
    __syncthreads();

    const float* qrow = qkv + (((size_t)0 * NWIN + w) * NHEADS + h) * head_stride + tid * HD;
    ull q2[12];
#pragma unroll
    for (int i = 0; i < 12; ++i) {
        float2 v = *(const float2*)(qrow + 2 * i);
        q2[i] = pk2(v.x, v.y);
    }
    const int gi = grp[tid];

    ull o2[12];
#pragma unroll
    for (int i = 0; i < 12; ++i) o2[i] = 0ULL;
    float l = 0.f;

    const ull* ksm = (const ull*)ks;
    const ull* vsm = (const ull*)vs;

    for (int j = 0; j < NTOK; ++j) {
        const ull* k2 = ksm + j * 12;
        ull dp = 0ULL;
#pragma unroll
        for (int i = 0; i < 12; ++i) fma2(dp, q2[i], k2[i]);
        float slo, shi; unpk2(slo, shi, dp);
        float s = slo + shi;
        s = (grp[j] == gi) ? s : s - 100.f;
        float p = __expf(s);
        l += p;
        ull pp = pk2(p, p);
        const ull* v2 = vsm + j * 12;
#pragma unroll
        for (int i = 0; i < 12; ++i) fma2(o2[i], pp, v2[i]);
    }
    float inv = 1.f / l;
    float* op = attnout + ((size_t)w * NTOK + tid) * CDIM + h * HD;
#pragma unroll
    for (int i = 0; i < 12; ++i) {
        float a, b; unpk2(a, b, o2[i]);
        op[2 * i] = a * inv; op[2 * i + 1] = b * inv;
    }
}

// ---------------------------------------------------------------------------
extern "C" void kernel_launch(void* const* d_in, const int* in_sizes, int n_in,
                              void* d_out, int out_size) {
    (void)in_sizes; (void)n_in; (void)out_size;
    const float* x       = (const float*)d_in[0];
    const float* norm1_g = (const float*)d_in[2];
    const float* norm1_b = (const float*)d_in[3];
    const float* qkv_w   = (const float*)d_in[4];
    const float* qkv_b   = (const float*)d_in[5];
    const float* proj_w  = (const float*)d_in[6];
    const float* proj_b  = (const float*)d_in[7];
    const float* norm2_g = (const float*)d_in[8];
    const float* norm2_b = (const float*)d_in[9];
    const float* fc1_w   = (const float*)d_in[10];
    const float* fc1_b   = (const float*)d_in[11];
    const float* fc2_w   = (const float*)d_in[12];
    const float* fc2_b   = (const float*)d_in[13];
    float* out = (float*)d_out;

    float *xw, *qkv, *attn, *x2, *xn2, *hbuf;
    cudaGetSymbolAddress((void**)&xw,   g_xw);
    cudaGetSymbolAddress((void**)&qkv,  g_qkv);
    cudaGetSymbolAddress((void**)&attn, g_attn);
    cudaGetSymbolAddress((void**)&x2,   g_x2);
    cudaGetSymbolAddress((void**)&xn2,  g_xn2);
    cudaGetSymbolAddress((void**)&hbuf, g_h);

    const int attn_smem = (2 * NTOK * HD) * 4 + 256;
    cudaFuncSetAttribute(attn_kernel, cudaFuncAttributeMaxDynamicSharedMemorySize, attn_smem);

    ln_kernel<<<TOKENS / 8, 256>>>(x, norm1_g, norm1_b, xw, 1);
    gemm_tc<EPI_QKV><<<dim3(TOKENS / BMX, 3), 256>>>(xw, CDIM, CDIM, qkv_w, qkv_b, nullptr, qkv);
    attn_kernel<<<dim3(NWIN, NHEADS), 256, attn_smem>>>(qkv, attn);
    gemm_tc<EPI_PROJ><<<dim3(TOKENS / BMX, 1), 256>>>(attn, CDIM, CDIM, proj_w, proj_b, x, x2);
    ln_kernel<<<TOKENS / 8, 256>>>(x2, norm2_g, norm2_b, xn2, 0);
    gemm_tc<EPI_FC1><<<dim3(TOKENS / BMX, HIDDEN_DIM / BNX), 256>>>(xn2, CDIM, CDIM, fc1_w, fc1_b, nullptr, hbuf);
    gemm_tc<EPI_FC2><<<dim3(TOKENS / BMX, 1), 256>>>(hbuf, HIDDEN_DIM, HIDDEN_DIM, fc2_w, fc2_b, x2, out);
}